// round 1
// baseline (speedup 1.0000x reference)
#include <cuda_runtime.h>
#include <math.h>

// Problem constants
#define B_   8
#define S_   2048
#define D_   1024          // INPUT_SZ == HIDDEN_SZ
#define MTOT (B_ * S_)     // 16384

// GEMM tiling
#define BM 128
#define BN 128
#define BK 16
#define TM 8
#define TN 8

// Scratch (device globals: allocation-free scratch per harness rules)
__device__ float g_x[(size_t)MTOT * D_];            // 64 MiB: x = x_batch @ lin_w^T + b
__device__ float g_q[(size_t)MTOT * D_];            // 64 MiB: Q
__device__ float g_s[(size_t)B_ * S_ * S_];         // 128 MiB: S / P (softmax in place)

// ---------------------------------------------------------------------------
// Templated SGEMM:
//   B_TRANS:     B is [N,K] row-major (C = A * B^T), else B is [K,N] (C = A * B)
//   CAUSAL_SKIP: skip blocks entirely above the causal diagonal (for S = Q K^T)
//   CAUSAL_K:    limit the K loop to k <= block's max row (for F = P V, P is
//                zero above the diagonal so those K tiles contribute nothing)
// C is always [M,N] row-major with leading dim N. Optional bias added per col.
// Batched via blockIdx.z with element strides.
// ---------------------------------------------------------------------------
template<bool B_TRANS, bool CAUSAL_SKIP, bool CAUSAL_K>
__global__ __launch_bounds__(256)
void sgemm_kernel(const float* __restrict__ A, const float* __restrict__ Bm,
                  const float* __restrict__ bias, float* __restrict__ C,
                  int M, int N, int K,
                  size_t strideA, size_t strideB, size_t strideC)
{
    const int bn = blockIdx.x;
    const int bm = blockIdx.y;
    const int bz = blockIdx.z;

    if (CAUSAL_SKIP) {
        // block columns all strictly greater than block's max row -> fully masked
        if (bn * BN > bm * BM + (BM - 1)) return;
    }

    A  += (size_t)bz * strideA;
    Bm += (size_t)bz * strideB;
    C  += (size_t)bz * strideC;

    __shared__ float As[BK][BM];
    __shared__ float Bs[BK][BN];

    const int tid = threadIdx.x;
    const int tx = tid % 16;   // column group (TN)
    const int ty = tid / 16;   // row group (TM)

    float acc[TM][TN];
#pragma unroll
    for (int i = 0; i < TM; i++)
#pragma unroll
        for (int j = 0; j < TN; j++) acc[i][j] = 0.f;

    int kmax = K;
    if (CAUSAL_K) {
        int lim = (bm + 1) * BM;       // rows in this block are <= bm*BM+127,
        kmax = lim < K ? lim : K;      // so columns of P beyond that are zero
    }

    // Loader indices (all dims here are multiples of tile sizes; no bounds checks)
    const int a_row = tid / 4;          // 0..63
    const int a_col = (tid % 4) * 4;    // 0,4,8,12
    const int b_row = tid / 32;         // 0..7   (NN loader)
    const int b_col = (tid % 32) * 4;   // 0..124 (NN loader)

    for (int k0 = 0; k0 < kmax; k0 += BK) {
        // --- load A tile (transpose into As[k][m]) ---
#pragma unroll
        for (int i = 0; i < 2; i++) {
            int r = a_row + i * 64;
            float4 v = *(const float4*)(A + (size_t)(bm * BM + r) * K + k0 + a_col);
            As[a_col + 0][r] = v.x;
            As[a_col + 1][r] = v.y;
            As[a_col + 2][r] = v.z;
            As[a_col + 3][r] = v.w;
        }
        // --- load B tile ---
        if (B_TRANS) {
            // B is [N,K]: rows are n, transpose into Bs[k][n]
#pragma unroll
            for (int i = 0; i < 2; i++) {
                int r = a_row + i * 64;
                float4 v = *(const float4*)(Bm + (size_t)(bn * BN + r) * K + k0 + a_col);
                Bs[a_col + 0][r] = v.x;
                Bs[a_col + 1][r] = v.y;
                Bs[a_col + 2][r] = v.z;
                Bs[a_col + 3][r] = v.w;
            }
        } else {
            // B is [K,N]: direct copy rows of k
#pragma unroll
            for (int i = 0; i < 2; i++) {
                int kr = b_row + i * 8;
                float4 v = *(const float4*)(Bm + (size_t)(k0 + kr) * N + bn * BN + b_col);
                *(float4*)&Bs[kr][b_col] = v;
            }
        }
        __syncthreads();

#pragma unroll
        for (int kk = 0; kk < BK; kk++) {
            float a[TM], b[TN];
#pragma unroll
            for (int i = 0; i < TM; i++) a[i] = As[kk][ty * TM + i];
#pragma unroll
            for (int j = 0; j < TN; j++) b[j] = Bs[kk][tx * TN + j];
#pragma unroll
            for (int i = 0; i < TM; i++)
#pragma unroll
                for (int j = 0; j < TN; j++)
                    acc[i][j] += a[i] * b[j];
        }
        __syncthreads();
    }

    // --- epilogue ---
#pragma unroll
    for (int i = 0; i < TM; i++) {
        int row = bm * BM + ty * TM + i;
#pragma unroll
        for (int j = 0; j < TN; j += 4) {
            int col = bn * BN + tx * TN + j;
            float4 v;
            v.x = acc[i][j + 0];
            v.y = acc[i][j + 1];
            v.z = acc[i][j + 2];
            v.w = acc[i][j + 3];
            if (bias) {
                v.x += bias[col + 0];
                v.y += bias[col + 1];
                v.z += bias[col + 2];
                v.w += bias[col + 3];
            }
            *(float4*)(C + (size_t)row * N + col) = v;
        }
    }
}

// ---------------------------------------------------------------------------
// Causal row softmax, in place on S -> P. Row q of batch b has q+1 valid
// entries; entries beyond the diagonal are written as 0 so the subsequent
// P @ V GEMM needs no masking.
// ---------------------------------------------------------------------------
__global__ __launch_bounds__(256)
void softmax_causal_kernel(float* __restrict__ S)
{
    const int q = blockIdx.x;
    const int b = blockIdx.y;
    const int L = q + 1;
    float* row = S + ((size_t)b * S_ + q) * S_;
    const int tid = threadIdx.x;

    __shared__ float red[256];

    float lmax = -1e30f;
    for (int k = tid; k < L; k += 256) lmax = fmaxf(lmax, row[k]);
    red[tid] = lmax;
    __syncthreads();
    for (int s = 128; s > 0; s >>= 1) {
        if (tid < s) red[tid] = fmaxf(red[tid], red[tid + s]);
        __syncthreads();
    }
    const float gmax = red[0];
    __syncthreads();

    float lsum = 0.f;
    for (int k = tid; k < L; k += 256) lsum += expf(row[k] - gmax);
    red[tid] = lsum;
    __syncthreads();
    for (int s = 128; s > 0; s >>= 1) {
        if (tid < s) red[tid] += red[tid + s];
        __syncthreads();
    }
    const float inv = 1.f / red[0];

    for (int k = tid; k < S_; k += 256)
        row[k] = (k < L) ? expf(row[k] - gmax) * inv : 0.f;
}

// ---------------------------------------------------------------------------
extern "C" void kernel_launch(void* const* d_in, const int* in_sizes, int n_in,
                              void* d_out, int out_size)
{
    (void)in_sizes; (void)n_in; (void)out_size;

    const float* x_batch = (const float*)d_in[0];  // [8,2048,1024]
    const float* lin_w   = (const float*)d_in[1];  // [1024,1024] (out,in)
    const float* lin_b   = (const float*)d_in[2];  // [1024]
    const float* W_q     = (const float*)d_in[3];  // [1024,1024]
    const float* W_k     = (const float*)d_in[4];
    const float* W_v     = (const float*)d_in[5];

    float* F  = (float*)d_out;                         // [8,2048,1024]
    float* cK = F  + (size_t)MTOT * D_;                // cache[0] = K
    float* cV = cK + (size_t)MTOT * D_;                // cache[1] = V

    float *gx, *gq, *gs;
    cudaGetSymbolAddress((void**)&gx, g_x);
    cudaGetSymbolAddress((void**)&gq, g_q);
    cudaGetSymbolAddress((void**)&gs, g_s);

    const dim3 blk(256);

    // 1) x = x_batch @ lin_w^T + b   (M=16384, N=1024, K=1024, NT)
    sgemm_kernel<true, false, false><<<dim3(D_ / BN, MTOT / BM), blk>>>(
        x_batch, lin_w, lin_b, gx, MTOT, D_, D_, 0, 0, 0);

    // 2) Q = x @ W_q ; K = x @ W_k ; V = x @ W_v  (NN). K/V land in the cache.
    sgemm_kernel<false, false, false><<<dim3(D_ / BN, MTOT / BM), blk>>>(
        gx, W_q, nullptr, gq, MTOT, D_, D_, 0, 0, 0);
    sgemm_kernel<false, false, false><<<dim3(D_ / BN, MTOT / BM), blk>>>(
        gx, W_k, nullptr, cK, MTOT, D_, D_, 0, 0, 0);
    sgemm_kernel<false, false, false><<<dim3(D_ / BN, MTOT / BM), blk>>>(
        gx, W_v, nullptr, cV, MTOT, D_, D_, 0, 0, 0);

    // 3) S = Q @ K^T  per batch (NT, causal block skip)
    sgemm_kernel<true, true, false><<<dim3(S_ / BN, S_ / BM, B_), blk>>>(
        gq, cK, nullptr, gs, S_, S_, D_,
        (size_t)S_ * D_, (size_t)S_ * D_, (size_t)S_ * S_);

    // 4) P = causal_softmax(S), in place, zeros above diagonal
    softmax_causal_kernel<<<dim3(S_, B_), blk>>>(gs);

    // 5) F = P @ V  per batch (NN, K loop causally limited)
    sgemm_kernel<false, false, true><<<dim3(D_ / BN, S_ / BM, B_), blk>>>(
        gs, cV, nullptr, F, S_, D_, S_,
        (size_t)S_ * S_, (size_t)S_ * D_, (size_t)S_ * D_);
}

// round 3
// speedup vs baseline: 1.2726x; 1.2726x over previous
#include <cuda_runtime.h>
#include <math.h>
#include <stdint.h>

// Problem constants
#define B_   8
#define S_   2048
#define D_   1024
#define MTOT (B_ * S_)     // 16384

// GEMM tiling
#define BM 128
#define BN 128
#define BK 16
#define PAD 4

// Scratch (device globals: allocation-free scratch per harness rules)
__device__ float g_x[(size_t)MTOT * D_];            // 64 MiB
__device__ float g_q[(size_t)MTOT * D_];            // 64 MiB
__device__ float g_s[(size_t)B_ * S_ * S_];         // 128 MiB

__device__ __forceinline__ uint32_t f2tf32(float x) {
    uint32_t r;
    asm("cvt.rna.tf32.f32 %0, %1;" : "=r"(r) : "f"(x));
    return r;
}

__device__ __forceinline__ void mma_tf32(float& c0, float& c1, float& c2, float& c3,
                                         uint32_t a0, uint32_t a1, uint32_t a2, uint32_t a3,
                                         uint32_t b0, uint32_t b1) {
    asm volatile(
        "mma.sync.aligned.m16n8k8.row.col.f32.tf32.tf32.f32 "
        "{%0,%1,%2,%3}, {%4,%5,%6,%7}, {%8,%9}, {%0,%1,%2,%3};"
        : "+f"(c0), "+f"(c1), "+f"(c2), "+f"(c3)
        : "r"(a0), "r"(a1), "r"(a2), "r"(a3), "r"(b0), "r"(b1));
}

// ---------------------------------------------------------------------------
// TF32 tensor-core GEMM. C[M,N] = A[M,K] * B (+bias).
//   SPLIT=3: 3xTF32 (hi*hi + hi*lo + lo*hi) ~ fp32 accuracy
//   SPLIT=1: plain tf32
//   B_TRANS: B is [N,K] row-major (C = A*B^T), else [K,N]
//   CAUSAL_SKIP: skip fully-masked blocks (S = Q K^T)
//   CAUSAL_K: limit K loop to block's max row (F = P V; P zero above diag)
// Block 128x128, 8 warps (2 in M x 4 in N), warp tile 64x32.
// ---------------------------------------------------------------------------
template<int SPLIT, bool B_TRANS, bool CAUSAL_SKIP, bool CAUSAL_K>
__global__ __launch_bounds__(256, 2)
void mma_gemm(const float* __restrict__ A, const float* __restrict__ Bm,
              const float* __restrict__ bias, float* __restrict__ C,
              int M, int N, int K,
              size_t strideA, size_t strideB, size_t strideC)
{
    const int bn = blockIdx.x;
    const int bm = blockIdx.y;
    const int bz = blockIdx.z;

    if (CAUSAL_SKIP) {
        if (bn * BN > bm * BM + (BM - 1)) return;
    }

    A  += (size_t)bz * strideA;
    Bm += (size_t)bz * strideB;
    C  += (size_t)bz * strideC;

    __shared__ uint32_t Ah[BK][BM + PAD];
    __shared__ uint32_t Al[BK][BM + PAD];
    __shared__ uint32_t Bh[BK][BN + PAD];
    __shared__ uint32_t Bl[BK][BN + PAD];

    const int tid  = threadIdx.x;
    const int lane = tid & 31;
    const int warp = tid >> 5;
    const int wm = (warp >> 2) * 64;   // warp row base within block (0,64)
    const int wn = (warp & 3) * 32;    // warp col base within block (0..96)
    const int lg = lane >> 2;          // 0..7
    const int lk = lane & 3;           // 0..3

    float acc[4][4][4];
#pragma unroll
    for (int i = 0; i < 4; i++)
#pragma unroll
        for (int j = 0; j < 4; j++)
#pragma unroll
            for (int r = 0; r < 4; r++) acc[i][j][r] = 0.f;

    int kmax = K;
    if (CAUSAL_K) {
        int lim = (bm + 1) * BM;
        kmax = lim < K ? lim : K;
    }

    // loader indices
    const int lrow = tid >> 2;          // 0..63
    const int lcol = (tid & 3) * 4;     // 0,4,8,12
    const int bkr  = tid >> 5;          // 0..7
    const int bnc  = (tid & 31) * 4;    // 0..124

    for (int k0 = 0; k0 < kmax; k0 += BK) {
        // ---- load + split A tile [BM x BK] -> Ah/Al[k][m] ----
#pragma unroll
        for (int i = 0; i < 2; i++) {
            int r = lrow + i * 64;
            float4 v = *(const float4*)(A + (size_t)(bm * BM + r) * K + k0 + lcol);
            float xs[4] = {v.x, v.y, v.z, v.w};
#pragma unroll
            for (int j = 0; j < 4; j++) {
                uint32_t h = f2tf32(xs[j]);
                Ah[lcol + j][r] = h;
                if (SPLIT == 3) {
                    float lo = xs[j] - __uint_as_float(h);
                    Al[lcol + j][r] = f2tf32(lo);
                }
            }
        }
        // ---- load + split B tile -> Bh/Bl[k][n] ----
        if (B_TRANS) {
#pragma unroll
            for (int i = 0; i < 2; i++) {
                int r = lrow + i * 64;
                float4 v = *(const float4*)(Bm + (size_t)(bn * BN + r) * K + k0 + lcol);
                float xs[4] = {v.x, v.y, v.z, v.w};
#pragma unroll
                for (int j = 0; j < 4; j++) {
                    uint32_t h = f2tf32(xs[j]);
                    Bh[lcol + j][r] = h;
                    if (SPLIT == 3) {
                        float lo = xs[j] - __uint_as_float(h);
                        Bl[lcol + j][r] = f2tf32(lo);
                    }
                }
            }
        } else {
#pragma unroll
            for (int i = 0; i < 2; i++) {
                int kr = bkr + i * 8;
                float4 v = *(const float4*)(Bm + (size_t)(k0 + kr) * N + bn * BN + bnc);
                float xs[4] = {v.x, v.y, v.z, v.w};
#pragma unroll
                for (int j = 0; j < 4; j++) {
                    uint32_t h = f2tf32(xs[j]);
                    Bh[kr][bnc + j] = h;
                    if (SPLIT == 3) {
                        float lo = xs[j] - __uint_as_float(h);
                        Bl[kr][bnc + j] = f2tf32(lo);
                    }
                }
            }
        }
        __syncthreads();

        // ---- compute: 2 k-steps of 8 ----
#pragma unroll
        for (int ks = 0; ks < BK; ks += 8) {
            uint32_t bh[4][2], bl[4][2];
#pragma unroll
            for (int ni = 0; ni < 4; ni++) {
                int n = wn + ni * 8 + lg;
                bh[ni][0] = Bh[ks + lk][n];
                bh[ni][1] = Bh[ks + lk + 4][n];
                if (SPLIT == 3) {
                    bl[ni][0] = Bl[ks + lk][n];
                    bl[ni][1] = Bl[ks + lk + 4][n];
                }
            }
#pragma unroll
            for (int mi = 0; mi < 4; mi++) {
                int r0 = wm + mi * 16 + lg;
                uint32_t ah0 = Ah[ks + lk][r0];
                uint32_t ah1 = Ah[ks + lk][r0 + 8];
                uint32_t ah2 = Ah[ks + lk + 4][r0];
                uint32_t ah3 = Ah[ks + lk + 4][r0 + 8];
                uint32_t al0 = 0, al1 = 0, al2 = 0, al3 = 0;
                if (SPLIT == 3) {
                    al0 = Al[ks + lk][r0];
                    al1 = Al[ks + lk][r0 + 8];
                    al2 = Al[ks + lk + 4][r0];
                    al3 = Al[ks + lk + 4][r0 + 8];
                }
#pragma unroll
                for (int ni = 0; ni < 4; ni++) {
                    float* c = acc[mi][ni];
                    if (SPLIT == 3) {
                        mma_tf32(c[0], c[1], c[2], c[3],
                                 ah0, ah1, ah2, ah3, bl[ni][0], bl[ni][1]);
                        mma_tf32(c[0], c[1], c[2], c[3],
                                 al0, al1, al2, al3, bh[ni][0], bh[ni][1]);
                    }
                    mma_tf32(c[0], c[1], c[2], c[3],
                             ah0, ah1, ah2, ah3, bh[ni][0], bh[ni][1]);
                }
            }
        }
        __syncthreads();
    }

    // ---- epilogue ----
#pragma unroll
    for (int mi = 0; mi < 4; mi++) {
#pragma unroll
        for (int ni = 0; ni < 4; ni++) {
            int r = bm * BM + wm + mi * 16 + lg;
            int c = bn * BN + wn + ni * 8 + lk * 2;
            float bx = 0.f, by = 0.f;
            if (bias) { bx = bias[c]; by = bias[c + 1]; }
            float2 v0 = make_float2(acc[mi][ni][0] + bx, acc[mi][ni][1] + by);
            float2 v1 = make_float2(acc[mi][ni][2] + bx, acc[mi][ni][3] + by);
            *(float2*)(C + (size_t)r * N + c)       = v0;
            *(float2*)(C + (size_t)(r + 8) * N + c) = v1;
        }
    }
}

// ---------------------------------------------------------------------------
// Causal row softmax, in place. Row staged in smem: 1 global read + 1 write.
// Entries beyond the diagonal written as 0.
// ---------------------------------------------------------------------------
__global__ __launch_bounds__(256)
void softmax_causal_kernel(float* __restrict__ S)
{
    const int q = blockIdx.x;
    const int b = blockIdx.y;
    const int L = q + 1;
    float* row = S + ((size_t)b * S_ + q) * S_;
    const int tid  = threadIdx.x;
    const int lane = tid & 31;
    const int warp = tid >> 5;

    __shared__ float buf[S_];
    __shared__ float red[8];

    // load + running max (only k < L participate)
    float lmax = -1e30f;
    for (int k4 = tid * 4; k4 < S_; k4 += 1024) {
        float4 v = *(const float4*)(row + k4);
        buf[k4 + 0] = v.x; buf[k4 + 1] = v.y; buf[k4 + 2] = v.z; buf[k4 + 3] = v.w;
        if (k4 + 0 < L) lmax = fmaxf(lmax, v.x);
        if (k4 + 1 < L) lmax = fmaxf(lmax, v.y);
        if (k4 + 2 < L) lmax = fmaxf(lmax, v.z);
        if (k4 + 3 < L) lmax = fmaxf(lmax, v.w);
    }
#pragma unroll
    for (int s = 16; s > 0; s >>= 1)
        lmax = fmaxf(lmax, __shfl_xor_sync(0xffffffffu, lmax, s));
    if (lane == 0) red[warp] = lmax;
    __syncthreads();
    float gmax = fmaxf(fmaxf(red[0], red[1]), fmaxf(red[2], red[3]));
    gmax = fmaxf(gmax, fmaxf(fmaxf(red[4], red[5]), fmaxf(red[6], red[7])));
    __syncthreads();

    // exp + sum (stores 0 beyond L)
    float lsum = 0.f;
    for (int k4 = tid * 4; k4 < S_; k4 += 1024) {
#pragma unroll
        for (int j = 0; j < 4; j++) {
            int k = k4 + j;
            float e = (k < L) ? expf(buf[k] - gmax) : 0.f;
            buf[k] = e;
            lsum += e;
        }
    }
#pragma unroll
    for (int s = 16; s > 0; s >>= 1)
        lsum += __shfl_xor_sync(0xffffffffu, lsum, s);
    if (lane == 0) red[warp] = lsum;
    __syncthreads();
    float gsum = red[0] + red[1] + red[2] + red[3] + red[4] + red[5] + red[6] + red[7];
    const float inv = 1.f / gsum;

    for (int k4 = tid * 4; k4 < S_; k4 += 1024) {
        float4 v = make_float4(buf[k4] * inv, buf[k4 + 1] * inv,
                               buf[k4 + 2] * inv, buf[k4 + 3] * inv);
        *(float4*)(row + k4) = v;
    }
}

// ---------------------------------------------------------------------------
extern "C" void kernel_launch(void* const* d_in, const int* in_sizes, int n_in,
                              void* d_out, int out_size)
{
    (void)in_sizes; (void)n_in; (void)out_size;

    const float* x_batch = (const float*)d_in[0];
    const float* lin_w   = (const float*)d_in[1];
    const float* lin_b   = (const float*)d_in[2];
    const float* W_q     = (const float*)d_in[3];
    const float* W_k     = (const float*)d_in[4];
    const float* W_v     = (const float*)d_in[5];

    float* F  = (float*)d_out;
    float* cK = F  + (size_t)MTOT * D_;
    float* cV = cK + (size_t)MTOT * D_;

    float *gx, *gq, *gs;
    cudaGetSymbolAddress((void**)&gx, g_x);
    cudaGetSymbolAddress((void**)&gq, g_q);
    cudaGetSymbolAddress((void**)&gs, g_s);

    const dim3 blk(256);

    // 1) x = x_batch @ lin_w^T + b   (3xTF32)
    mma_gemm<3, true, false, false><<<dim3(D_ / BN, MTOT / BM), blk>>>(
        x_batch, lin_w, lin_b, gx, MTOT, D_, D_, 0, 0, 0);

    // 2) Q, K, V (3xTF32); K/V land directly in the output cache
    mma_gemm<3, false, false, false><<<dim3(D_ / BN, MTOT / BM), blk>>>(
        gx, W_q, nullptr, gq, MTOT, D_, D_, 0, 0, 0);
    mma_gemm<3, false, false, false><<<dim3(D_ / BN, MTOT / BM), blk>>>(
        gx, W_k, nullptr, cK, MTOT, D_, D_, 0, 0, 0);
    mma_gemm<3, false, false, false><<<dim3(D_ / BN, MTOT / BM), blk>>>(
        gx, W_v, nullptr, cV, MTOT, D_, D_, 0, 0, 0);

    // 3) S = Q @ K^T (3xTF32, causal block skip)
    mma_gemm<3, true, true, false><<<dim3(S_ / BN, S_ / BM, B_), blk>>>(
        gq, cK, nullptr, gs, S_, S_, D_,
        (size_t)S_ * D_, (size_t)S_ * D_, (size_t)S_ * S_);

    // 4) P = causal_softmax(S)
    softmax_causal_kernel<<<dim3(S_, B_), blk>>>(gs);

    // 5) F = P @ V (plain tf32, causal K limit)
    mma_gemm<1, false, false, true><<<dim3(D_ / BN, S_ / BM, B_), blk>>>(
        gs, cV, nullptr, F, S_, D_, S_,
        (size_t)S_ * S_, (size_t)S_ * D_, (size_t)S_ * D_);
}

// round 6
// speedup vs baseline: 1.3347x; 1.0489x over previous
#include <cuda_runtime.h>
#include <math.h>
#include <stdint.h>

// Problem constants
#define B_   8
#define S_   2048
#define D_   1024
#define MTOT (B_ * S_)     // 16384

// GEMM tiling
#define BM 128
#define BN 128
#define BK 16

// Conflict-free XOR swizzle for k-major [BK][128] operand tiles.
// phys word = k*128 + (m ^ (((k&3) ^ ((k>>2)&3)) << 3))
// - compute reads (lanes vary m bits0-2 via lg, k bits0-1 via lk): conflict-free
// - loader stores (lanes vary m bits0-2 via lane>>2, k bits2-3 via lane&3): conflict-free
#define SW16(k) (((((k) & 3) ^ (((k) >> 2) & 3))) << 3)
#define IDX(k, m) (((k) << 7) + ((m) ^ SW16(k)))

// Scratch (device globals: allocation-free scratch per harness rules)
__device__ float g_x[(size_t)MTOT * D_];            // 64 MiB
__device__ float g_q[(size_t)MTOT * D_];            // 64 MiB
__device__ float g_s[(size_t)B_ * S_ * S_];         // 128 MiB

__device__ __forceinline__ uint32_t f2tf32(float x) {
    uint32_t r;
    asm("cvt.rna.tf32.f32 %0, %1;" : "=r"(r) : "f"(x));
    return r;
}

__device__ __forceinline__ void mma_tf32(float& c0, float& c1, float& c2, float& c3,
                                         uint32_t a0, uint32_t a1, uint32_t a2, uint32_t a3,
                                         uint32_t b0, uint32_t b1) {
    asm volatile(
        "mma.sync.aligned.m16n8k8.row.col.f32.tf32.tf32.f32 "
        "{%0,%1,%2,%3}, {%4,%5,%6,%7}, {%8,%9}, {%0,%1,%2,%3};"
        : "+f"(c0), "+f"(c1), "+f"(c2), "+f"(c3)
        : "r"(a0), "r"(a1), "r"(a2), "r"(a3), "r"(b0), "r"(b1));
}

// ---------------------------------------------------------------------------
// TF32 tensor-core GEMM. C[M,N] = A[M,K] * B (+bias).
//   SPLIT=3: 3xTF32 (hi*hi + hi*lo + lo*hi) ~ fp32 accuracy
//   SPLIT=1: plain tf32
//   B_TRANS: B is [N,K] row-major (C = A*B^T), else [K,N]
//   CAUSAL_SKIP: skip fully-masked blocks (S = Q K^T)
//   CAUSAL_K: limit K loop to block's max row (F = P V; P zero above diag)
// Block 128x128, 8 warps (2 in M x 4 in N), warp tile 64x32.
// ---------------------------------------------------------------------------
template<int SPLIT, bool B_TRANS, bool CAUSAL_SKIP, bool CAUSAL_K>
__global__ __launch_bounds__(256, 2)
void mma_gemm(const float* __restrict__ A, const float* __restrict__ Bm,
              const float* __restrict__ bias, float* __restrict__ C,
              int M, int N, int K,
              size_t strideA, size_t strideB, size_t strideC)
{
    const int bn = blockIdx.x;
    const int bm = blockIdx.y;
    const int bz = blockIdx.z;

    if (CAUSAL_SKIP) {
        if (bn * BN > bm * BM + (BM - 1)) return;
    }

    A  += (size_t)bz * strideA;
    Bm += (size_t)bz * strideB;
    C  += (size_t)bz * strideC;

    __shared__ uint32_t Ah[BK * BM];
    __shared__ uint32_t Al[BK * BM];
    __shared__ uint32_t Bh[BK * BN];
    __shared__ uint32_t Bl[BK * BN];

    const int tid  = threadIdx.x;
    const int lane = tid & 31;
    const int warp = tid >> 5;
    const int wm = (warp >> 2) * 64;   // warp row base within block (0,64)
    const int wn = (warp & 3) * 32;    // warp col base within block (0..96)
    const int lg = lane >> 2;          // 0..7
    const int lk = lane & 3;           // 0..3

    float acc[4][4][4];
#pragma unroll
    for (int i = 0; i < 4; i++)
#pragma unroll
        for (int j = 0; j < 4; j++)
#pragma unroll
            for (int r = 0; r < 4; r++) acc[i][j][r] = 0.f;

    int kmax = K;
    if (CAUSAL_K) {
        int lim = (bm + 1) * BM;
        kmax = lim < K ? lim : K;
    }

    // loader indices
    const int lrow = tid >> 2;          // 0..63
    const int lcol = (tid & 3) * 4;     // 0,4,8,12
    const int bkr  = tid >> 5;          // 0..7
    const int bnc  = (tid & 31) * 4;    // 0..124

    for (int k0 = 0; k0 < kmax; k0 += BK) {
        // ---- load + split A tile [BM x BK] -> Ah/Al swizzled k-major ----
#pragma unroll
        for (int i = 0; i < 2; i++) {
            int r = lrow + i * 64;
            float4 v = *(const float4*)(A + (size_t)(bm * BM + r) * K + k0 + lcol);
            float xs[4] = {v.x, v.y, v.z, v.w};
#pragma unroll
            for (int j = 0; j < 4; j++) {
                uint32_t h = f2tf32(xs[j]);
                Ah[IDX(lcol + j, r)] = h;
                if (SPLIT == 3) {
                    float lo = xs[j] - __uint_as_float(h);
                    Al[IDX(lcol + j, r)] = f2tf32(lo);
                }
            }
        }
        // ---- load + split B tile -> Bh/Bl swizzled k-major ----
        if (B_TRANS) {
#pragma unroll
            for (int i = 0; i < 2; i++) {
                int r = lrow + i * 64;
                float4 v = *(const float4*)(Bm + (size_t)(bn * BN + r) * K + k0 + lcol);
                float xs[4] = {v.x, v.y, v.z, v.w};
#pragma unroll
                for (int j = 0; j < 4; j++) {
                    uint32_t h = f2tf32(xs[j]);
                    Bh[IDX(lcol + j, r)] = h;
                    if (SPLIT == 3) {
                        float lo = xs[j] - __uint_as_float(h);
                        Bl[IDX(lcol + j, r)] = f2tf32(lo);
                    }
                }
            }
        } else {
#pragma unroll
            for (int i = 0; i < 2; i++) {
                int kr = bkr + i * 8;
                float4 v = *(const float4*)(Bm + (size_t)(k0 + kr) * N + bn * BN + bnc);
                // XOR only touches bits >=3: 4-block stays contiguous & aligned
                uint32_t* dst = &Bh[IDX(kr, bnc)];
                dst[0] = f2tf32(v.x); dst[1] = f2tf32(v.y);
                dst[2] = f2tf32(v.z); dst[3] = f2tf32(v.w);
                if (SPLIT == 3) {
                    uint32_t* dl = &Bl[IDX(kr, bnc)];
                    dl[0] = f2tf32(v.x - __uint_as_float(dst[0]));
                    dl[1] = f2tf32(v.y - __uint_as_float(dst[1]));
                    dl[2] = f2tf32(v.z - __uint_as_float(dst[2]));
                    dl[3] = f2tf32(v.w - __uint_as_float(dst[3]));
                }
            }
        }
        __syncthreads();

        // ---- compute: 2 k-steps of 8 ----
#pragma unroll
        for (int ks = 0; ks < BK; ks += 8) {
            uint32_t bh[4][2], bl[4][2];
#pragma unroll
            for (int ni = 0; ni < 4; ni++) {
                int n = wn + ni * 8 + lg;
                bh[ni][0] = Bh[IDX(ks + lk, n)];
                bh[ni][1] = Bh[IDX(ks + lk + 4, n)];
                if (SPLIT == 3) {
                    bl[ni][0] = Bl[IDX(ks + lk, n)];
                    bl[ni][1] = Bl[IDX(ks + lk + 4, n)];
                }
            }
#pragma unroll
            for (int mi = 0; mi < 4; mi++) {
                int r0 = wm + mi * 16 + lg;
                uint32_t ah0 = Ah[IDX(ks + lk, r0)];
                uint32_t ah1 = Ah[IDX(ks + lk, r0 + 8)];
                uint32_t ah2 = Ah[IDX(ks + lk + 4, r0)];
                uint32_t ah3 = Ah[IDX(ks + lk + 4, r0 + 8)];
                uint32_t al0 = 0, al1 = 0, al2 = 0, al3 = 0;
                if (SPLIT == 3) {
                    al0 = Al[IDX(ks + lk, r0)];
                    al1 = Al[IDX(ks + lk, r0 + 8)];
                    al2 = Al[IDX(ks + lk + 4, r0)];
                    al3 = Al[IDX(ks + lk + 4, r0 + 8)];
                }
#pragma unroll
                for (int ni = 0; ni < 4; ni++) {
                    float* c = acc[mi][ni];
                    if (SPLIT == 3) {
                        mma_tf32(c[0], c[1], c[2], c[3],
                                 ah0, ah1, ah2, ah3, bl[ni][0], bl[ni][1]);
                        mma_tf32(c[0], c[1], c[2], c[3],
                                 al0, al1, al2, al3, bh[ni][0], bh[ni][1]);
                    }
                    mma_tf32(c[0], c[1], c[2], c[3],
                             ah0, ah1, ah2, ah3, bh[ni][0], bh[ni][1]);
                }
            }
        }
        __syncthreads();
    }

    // ---- epilogue ----
#pragma unroll
    for (int mi = 0; mi < 4; mi++) {
#pragma unroll
        for (int ni = 0; ni < 4; ni++) {
            int r = bm * BM + wm + mi * 16 + lg;
            int c = bn * BN + wn + ni * 8 + lk * 2;
            float bx = 0.f, by = 0.f;
            if (bias) { bx = bias[c]; by = bias[c + 1]; }
            float2 v0 = make_float2(acc[mi][ni][0] + bx, acc[mi][ni][1] + by);
            float2 v1 = make_float2(acc[mi][ni][2] + bx, acc[mi][ni][3] + by);
            *(float2*)(C + (size_t)r * N + c)       = v0;
            *(float2*)(C + (size_t)(r + 8) * N + c) = v1;
        }
    }
}

// ---------------------------------------------------------------------------
// Causal row softmax, in place. Row staged in smem: 1 global read + 1 write.
// ---------------------------------------------------------------------------
__global__ __launch_bounds__(256)
void softmax_causal_kernel(float* __restrict__ S)
{
    const int q = blockIdx.x;
    const int b = blockIdx.y;
    const int L = q + 1;
    float* row = S + ((size_t)b * S_ + q) * S_;
    const int tid  = threadIdx.x;
    const int lane = tid & 31;
    const int warp = tid >> 5;

    __shared__ float buf[S_];
    __shared__ float red[8];

    float lmax = -1e30f;
    for (int k4 = tid * 4; k4 < S_; k4 += 1024) {
        float4 v = *(const float4*)(row + k4);
        buf[k4 + 0] = v.x; buf[k4 + 1] = v.y; buf[k4 + 2] = v.z; buf[k4 + 3] = v.w;
        if (k4 + 0 < L) lmax = fmaxf(lmax, v.x);
        if (k4 + 1 < L) lmax = fmaxf(lmax, v.y);
        if (k4 + 2 < L) lmax = fmaxf(lmax, v.z);
        if (k4 + 3 < L) lmax = fmaxf(lmax, v.w);
    }
#pragma unroll
    for (int s = 16; s > 0; s >>= 1)
        lmax = fmaxf(lmax, __shfl_xor_sync(0xffffffffu, lmax, s));
    if (lane == 0) red[warp] = lmax;
    __syncthreads();
    float gmax = fmaxf(fmaxf(red[0], red[1]), fmaxf(red[2], red[3]));
    gmax = fmaxf(gmax, fmaxf(fmaxf(red[4], red[5]), fmaxf(red[6], red[7])));
    __syncthreads();

    float lsum = 0.f;
    for (int k4 = tid * 4; k4 < S_; k4 += 1024) {
#pragma unroll
        for (int j = 0; j < 4; j++) {
            int k = k4 + j;
            float e = (k < L) ? expf(buf[k] - gmax) : 0.f;
            buf[k] = e;
            lsum += e;
        }
    }
#pragma unroll
    for (int s = 16; s > 0; s >>= 1)
        lsum += __shfl_xor_sync(0xffffffffu, lsum, s);
    if (lane == 0) red[warp] = lsum;
    __syncthreads();
    float gsum = red[0] + red[1] + red[2] + red[3] + red[4] + red[5] + red[6] + red[7];
    const float inv = 1.f / gsum;

    for (int k4 = tid * 4; k4 < S_; k4 += 1024) {
        float4 v = make_float4(buf[k4] * inv, buf[k4 + 1] * inv,
                               buf[k4 + 2] * inv, buf[k4 + 3] * inv);
        *(float4*)(row + k4) = v;
    }
}

// ---------------------------------------------------------------------------
extern "C" void kernel_launch(void* const* d_in, const int* in_sizes, int n_in,
                              void* d_out, int out_size)
{
    (void)in_sizes; (void)n_in; (void)out_size;

    const float* x_batch = (const float*)d_in[0];
    const float* lin_w   = (const float*)d_in[1];
    const float* lin_b   = (const float*)d_in[2];
    const float* W_q     = (const float*)d_in[3];
    const float* W_k     = (const float*)d_in[4];
    const float* W_v     = (const float*)d_in[5];

    float* F  = (float*)d_out;
    float* cK = F  + (size_t)MTOT * D_;
    float* cV = cK + (size_t)MTOT * D_;

    float *gx, *gq, *gs;
    cudaGetSymbolAddress((void**)&gx, g_x);
    cudaGetSymbolAddress((void**)&gq, g_q);
    cudaGetSymbolAddress((void**)&gs, g_s);

    const dim3 blk(256);

    // 1) x = x_batch @ lin_w^T + b   (3xTF32)
    mma_gemm<3, true, false, false><<<dim3(D_ / BN, MTOT / BM), blk>>>(
        x_batch, lin_w, lin_b, gx, MTOT, D_, D_, 0, 0, 0);

    // 2) Q, K, V (3xTF32); K/V land directly in the output cache
    mma_gemm<3, false, false, false><<<dim3(D_ / BN, MTOT / BM), blk>>>(
        gx, W_q, nullptr, gq, MTOT, D_, D_, 0, 0, 0);
    mma_gemm<3, false, false, false><<<dim3(D_ / BN, MTOT / BM), blk>>>(
        gx, W_k, nullptr, cK, MTOT, D_, D_, 0, 0, 0);
    mma_gemm<3, false, false, false><<<dim3(D_ / BN, MTOT / BM), blk>>>(
        gx, W_v, nullptr, cV, MTOT, D_, D_, 0, 0, 0);

    // 3) S = Q @ K^T (3xTF32, causal block skip)
    mma_gemm<3, true, true, false><<<dim3(S_ / BN, S_ / BM, B_), blk>>>(
        gq, cK, nullptr, gs, S_, S_, D_,
        (size_t)S_ * D_, (size_t)S_ * D_, (size_t)S_ * S_);

    // 4) P = causal_softmax(S)
    softmax_causal_kernel<<<dim3(S_, B_), blk>>>(gs);

    // 5) F = P @ V (plain tf32, causal K limit)
    mma_gemm<1, false, false, true><<<dim3(D_ / BN, S_ / BM, B_), blk>>>(
        gs, cV, nullptr, F, S_, D_, S_,
        (size_t)S_ * S_, (size_t)S_ * D_, (size_t)S_ * D_);
}

// round 8
// speedup vs baseline: 1.5725x; 1.1781x over previous
#include <cuda_runtime.h>
#include <math.h>
#include <stdint.h>

// Problem constants
#define B_   8
#define S_   2048
#define D_   1024
#define MTOT (B_ * S_)     // 16384

// GEMM tiling
#define BM 128
#define BN 128
#define BK 16

// ---- scratch (device globals; allocation-free) ----
__device__ float g_xbh[(size_t)MTOT * D_];  // x_batch hi -> later Q hi
__device__ float g_xbl[(size_t)MTOT * D_];  // x_batch lo -> later Q lo
__device__ float g_xh [(size_t)MTOT * D_];
__device__ float g_xl [(size_t)MTOT * D_];
__device__ float g_kh [(size_t)MTOT * D_];
__device__ float g_kl [(size_t)MTOT * D_];
__device__ float g_vr [(size_t)MTOT * D_];  // rna-rounded V
__device__ float g_s  [(size_t)B_ * S_ * S_];
__device__ float g_w0h[D_ * D_], g_w0l[D_ * D_];
__device__ float g_wqh[D_ * D_], g_wql[D_ * D_];
__device__ float g_wkh[D_ * D_], g_wkl[D_ * D_];
__device__ float g_wvh[D_ * D_], g_wvl[D_ * D_];

// ---- helpers ----
__device__ __forceinline__ uint32_t f2tf32(float x) {
    uint32_t r; asm("cvt.rna.tf32.f32 %0, %1;" : "=r"(r) : "f"(x));
    return r;
}
__device__ __forceinline__ float f2tff(float x) { return __uint_as_float(f2tf32(x)); }
__device__ __forceinline__ uint32_t s2u(const void* p) {
    uint32_t a;
    asm("{ .reg .u64 t; cvta.to.shared.u64 t, %1; cvt.u32.u64 %0, t; }" : "=r"(a) : "l"(p));
    return a;
}
__device__ __forceinline__ void cp16(uint32_t dst, const float* src) {
    asm volatile("cp.async.cg.shared.global [%0], [%1], 16;" :: "r"(dst), "l"(src) : "memory");
}
__device__ __forceinline__ void mma_tf32(float& c0, float& c1, float& c2, float& c3,
                                         uint32_t a0, uint32_t a1, uint32_t a2, uint32_t a3,
                                         uint32_t b0, uint32_t b1) {
    asm volatile(
        "mma.sync.aligned.m16n8k8.row.col.f32.tf32.tf32.f32 "
        "{%0,%1,%2,%3}, {%4,%5,%6,%7}, {%8,%9}, {%0,%1,%2,%3};"
        : "+f"(c0), "+f"(c1), "+f"(c2), "+f"(c3)
        : "r"(a0), "r"(a1), "r"(a2), "r"(a3), "r"(b0), "r"(b1));
}

// smem word layouts (conflict-free on fragment reads, 16B-chunk-preserving for cp.async)
// NT operand plane: [m][16 k-words], k swizzled by m
__device__ __forceinline__ int ntw(int m, int k) {
    return m * 16 + (k ^ (((m >> 1) & 3) << 2));
}
// NN B plane: [k][128 n-words], n swizzled by k
__device__ __forceinline__ int nnw(int k, int n) {
    return k * 128 + (n ^ ((k & 15) << 3));
}

// ---------------------------------------------------------------------------
// cp.async double-buffered TF32 tensor GEMM on pre-split planes.
// C tile (bm,bn) = A[M,K] * B (+bias). A planes row-major [.,K].
//   SPLIT=3: hi/lo planes for A and B, 3 mma terms. SPLIT=1: hi only.
//   B_TRANS: B planes are [N,K] (NT). else [K,N] (NN).
//   CAUSAL_SKIP / CAUSAL_K as before.
// Outputs (nullable): Cf fp32 (+bias), Ch/Cl split planes, Cr rounded plane.
// ---------------------------------------------------------------------------
template<int SPLIT, bool B_TRANS, bool CAUSAL_SKIP, bool CAUSAL_K>
__global__ __launch_bounds__(256, 2)
void mma_gemm(const float* __restrict__ Ah_, const float* __restrict__ Al_,
              const float* __restrict__ Bh_, const float* __restrict__ Bl_,
              const float* __restrict__ bias,
              float* __restrict__ Cf, float* __restrict__ Ch,
              float* __restrict__ Cl, float* __restrict__ Cr,
              int N, int K,
              size_t strideA, size_t strideB, size_t strideC)
{
    const int bn = blockIdx.x;
    const int bm = blockIdx.y;
    const int bz = blockIdx.z;
    if (CAUSAL_SKIP && bn * BN > bm * BM + (BM - 1)) return;

    const float* Abase  = Ah_ + (size_t)bz * strideA + (size_t)(bm * BM) * K;
    const float* Albase = (SPLIT == 3) ? Al_ + (size_t)bz * strideA + (size_t)(bm * BM) * K : nullptr;
    const float* Bbase, * Blbase = nullptr;
    if (B_TRANS) {
        Bbase = Bh_ + (size_t)bz * strideB + (size_t)(bn * BN) * K;
        if (SPLIT == 3) Blbase = Bl_ + (size_t)bz * strideB + (size_t)(bn * BN) * K;
    } else {
        Bbase = Bh_ + (size_t)bz * strideB;
        if (SPLIT == 3) Blbase = Bl_ + (size_t)bz * strideB;
    }

    extern __shared__ uint32_t sw[];
    const uint32_t smb = s2u(sw);
    // plane = 2048 words (8KB). Stage: [Ah][Al?][Bh][Bl?]
    const int AW = 0, ALW = 2048;
    const int BW  = (SPLIT == 3) ? 4096 : 2048;
    const int BLW = BW + 2048;
    const int STGW = (SPLIT == 3) ? 8192 : 4096;   // words per stage
    const uint32_t STGB = STGW * 4;
    const uint32_t PLB = 8192;                     // plane bytes

    const int tid  = threadIdx.x;
    const int lane = tid & 31;
    const int warp = tid >> 5;
    const int wm = (warp >> 2) * 64;
    const int wn = (warp & 3) * 32;
    const int lg = lane >> 2;
    const int lk = lane & 3;

    int kmax = K;
    if (CAUSAL_K) {
        int lim = (bm + 1) * BM;
        kmax = lim < K ? lim : K;
    }
    const int nit = kmax / BK;

    auto load_stage = [&](int s, int k0) {
        const uint32_t sb = smb + (uint32_t)s * STGB;
#pragma unroll
        for (int c0 = 0; c0 < 512; c0 += 256) {
            int c = c0 + tid;
            int m = c >> 2, g = c & 3;
            uint32_t d = sb + (uint32_t)(m * 64 + ((g ^ ((m >> 1) & 3)) << 4));
            const float* sa = Abase + (size_t)m * K + k0 + g * 4;
            cp16(d, sa);
            if (SPLIT == 3) cp16(d + PLB, Albase + (size_t)m * K + k0 + g * 4);
        }
        if (B_TRANS) {
#pragma unroll
            for (int c0 = 0; c0 < 512; c0 += 256) {
                int c = c0 + tid;
                int m = c >> 2, g = c & 3;
                uint32_t d = sb + (uint32_t)(BW * 4) +
                             (uint32_t)(m * 64 + ((g ^ ((m >> 1) & 3)) << 4));
                cp16(d, Bbase + (size_t)m * K + k0 + g * 4);
                if (SPLIT == 3) cp16(d + PLB, Blbase + (size_t)m * K + k0 + g * 4);
            }
        } else {
#pragma unroll
            for (int c0 = 0; c0 < 512; c0 += 256) {
                int c = c0 + tid;
                int k = c >> 5, ch = c & 31;
                uint32_t d = sb + (uint32_t)(BW * 4) +
                             (uint32_t)(k * 512 + (((ch ^ (k << 1)) & 31) << 4));
                const float* sb2 = Bbase + (size_t)(k0 + k) * N + bn * BN + ch * 4;
                cp16(d, sb2);
                if (SPLIT == 3) cp16(d + PLB, Blbase + (size_t)(k0 + k) * N + bn * BN + ch * 4);
            }
        }
        asm volatile("cp.async.commit_group;" ::: "memory");
    };

    float acc[4][4][4];
#pragma unroll
    for (int i = 0; i < 4; i++)
#pragma unroll
        for (int j = 0; j < 4; j++)
#pragma unroll
            for (int r = 0; r < 4; r++) acc[i][j][r] = 0.f;

    load_stage(0, 0);
    load_stage(1, BK);

    for (int i = 0; i < nit; i++) {
        if (i < nit - 1)
            asm volatile("cp.async.wait_group 1;" ::: "memory");
        else
            asm volatile("cp.async.wait_group 0;" ::: "memory");
        __syncthreads();

        const uint32_t* st = sw + (size_t)(i & 1) * STGW;

#pragma unroll
        for (int ks = 0; ks < BK; ks += 8) {
            uint32_t bh[4][2], bl[4][2];
#pragma unroll
            for (int ni = 0; ni < 4; ni++) {
                int n = wn + ni * 8 + lg;
                int w0, w1;
                if (B_TRANS) { w0 = ntw(n, ks + lk); w1 = ntw(n, ks + lk + 4); }
                else         { w0 = nnw(ks + lk, n); w1 = nnw(ks + lk + 4, n); }
                bh[ni][0] = st[BW + w0];
                bh[ni][1] = st[BW + w1];
                if (SPLIT == 3) {
                    bl[ni][0] = st[BLW + w0];
                    bl[ni][1] = st[BLW + w1];
                }
            }
#pragma unroll
            for (int mi = 0; mi < 4; mi++) {
                int m = wm + mi * 16 + lg;
                int wa0 = ntw(m,     ks + lk);
                int wa1 = ntw(m + 8, ks + lk);
                int wa2 = ntw(m,     ks + lk + 4);
                int wa3 = ntw(m + 8, ks + lk + 4);
                uint32_t ah0 = st[AW + wa0], ah1 = st[AW + wa1];
                uint32_t ah2 = st[AW + wa2], ah3 = st[AW + wa3];
                uint32_t al0 = 0, al1 = 0, al2 = 0, al3 = 0;
                if (SPLIT == 3) {
                    al0 = st[ALW + wa0]; al1 = st[ALW + wa1];
                    al2 = st[ALW + wa2]; al3 = st[ALW + wa3];
                }
#pragma unroll
                for (int ni = 0; ni < 4; ni++) {
                    float* c = acc[mi][ni];
                    if (SPLIT == 3) {
                        mma_tf32(c[0], c[1], c[2], c[3],
                                 ah0, ah1, ah2, ah3, bl[ni][0], bl[ni][1]);
                        mma_tf32(c[0], c[1], c[2], c[3],
                                 al0, al1, al2, al3, bh[ni][0], bh[ni][1]);
                    }
                    mma_tf32(c[0], c[1], c[2], c[3],
                             ah0, ah1, ah2, ah3, bh[ni][0], bh[ni][1]);
                }
            }
        }
        __syncthreads();
        if (i + 2 < nit) load_stage(i & 1, (i + 2) * BK);
    }

    // ---- epilogue ----
#pragma unroll
    for (int mi = 0; mi < 4; mi++) {
#pragma unroll
        for (int ni = 0; ni < 4; ni++) {
            int r = bm * BM + wm + mi * 16 + lg;
            int c = bn * BN + wn + ni * 8 + lk * 2;
            float bx = 0.f, by = 0.f;
            if (bias) { bx = bias[c]; by = bias[c + 1]; }
            float2 v0 = make_float2(acc[mi][ni][0] + bx, acc[mi][ni][1] + by);
            float2 v1 = make_float2(acc[mi][ni][2] + bx, acc[mi][ni][3] + by);
            const size_t o0 = (size_t)bz * strideC + (size_t)r * N + c;
            const size_t o1 = (size_t)bz * strideC + (size_t)(r + 8) * N + c;
            if (Cf) {
                *(float2*)(Cf + o0) = v0;
                *(float2*)(Cf + o1) = v1;
            }
            if (Ch) {
                float2 h0 = make_float2(f2tff(v0.x), f2tff(v0.y));
                float2 h1 = make_float2(f2tff(v1.x), f2tff(v1.y));
                *(float2*)(Ch + o0) = h0;
                *(float2*)(Ch + o1) = h1;
                *(float2*)(Cl + o0) = make_float2(f2tff(v0.x - h0.x), f2tff(v0.y - h0.y));
                *(float2*)(Cl + o1) = make_float2(f2tff(v1.x - h1.x), f2tff(v1.y - h1.y));
            }
            if (Cr) {
                *(float2*)(Cr + o0) = make_float2(f2tff(v0.x), f2tff(v0.y));
                *(float2*)(Cr + o1) = make_float2(f2tff(v1.x), f2tff(v1.y));
            }
        }
    }
}

// ---- elementwise hi/lo split ----
__global__ __launch_bounds__(256)
void split_k(const float4* __restrict__ src, float4* __restrict__ h4,
             float4* __restrict__ l4, int n4)
{
    int i = blockIdx.x * 256 + threadIdx.x;
    if (i >= n4) return;
    float4 v = src[i], h, l;
    h.x = f2tff(v.x); l.x = f2tff(v.x - h.x);
    h.y = f2tff(v.y); l.y = f2tff(v.y - h.y);
    h.z = f2tff(v.z); l.z = f2tff(v.z - h.z);
    h.w = f2tff(v.w); l.w = f2tff(v.w - h.w);
    h4[i] = h; l4[i] = l;
}

// ---- causal row softmax; writes rna-rounded P (exact under tf32 truncation) ----
__global__ __launch_bounds__(256)
void softmax_causal_kernel(float* __restrict__ S)
{
    const int q = blockIdx.x;
    const int b = blockIdx.y;
    const int L = q + 1;
    float* row = S + ((size_t)b * S_ + q) * S_;
    const int tid = threadIdx.x, lane = tid & 31, warp = tid >> 5;

    __shared__ float buf[S_];
    __shared__ float red[8];

    float lmax = -1e30f;
    for (int k4 = tid * 4; k4 < S_; k4 += 1024) {
        float4 v = *(const float4*)(row + k4);
        buf[k4+0] = v.x; buf[k4+1] = v.y; buf[k4+2] = v.z; buf[k4+3] = v.w;
        if (k4+0 < L) lmax = fmaxf(lmax, v.x);
        if (k4+1 < L) lmax = fmaxf(lmax, v.y);
        if (k4+2 < L) lmax = fmaxf(lmax, v.z);
        if (k4+3 < L) lmax = fmaxf(lmax, v.w);
    }
#pragma unroll
    for (int s = 16; s > 0; s >>= 1)
        lmax = fmaxf(lmax, __shfl_xor_sync(0xffffffffu, lmax, s));
    if (lane == 0) red[warp] = lmax;
    __syncthreads();
    float gmax = fmaxf(fmaxf(red[0], red[1]), fmaxf(red[2], red[3]));
    gmax = fmaxf(gmax, fmaxf(fmaxf(red[4], red[5]), fmaxf(red[6], red[7])));
    __syncthreads();

    float lsum = 0.f;
    for (int k4 = tid * 4; k4 < S_; k4 += 1024) {
#pragma unroll
        for (int j = 0; j < 4; j++) {
            int k = k4 + j;
            float e = (k < L) ? expf(buf[k] - gmax) : 0.f;
            buf[k] = e;
            lsum += e;
        }
    }
#pragma unroll
    for (int s = 16; s > 0; s >>= 1)
        lsum += __shfl_xor_sync(0xffffffffu, lsum, s);
    if (lane == 0) red[warp] = lsum;
    __syncthreads();
    const float inv = 1.f / (red[0]+red[1]+red[2]+red[3]+red[4]+red[5]+red[6]+red[7]);

    for (int k4 = tid * 4; k4 < S_; k4 += 1024) {
        float4 v = make_float4(f2tff(buf[k4] * inv),   f2tff(buf[k4+1] * inv),
                               f2tff(buf[k4+2] * inv), f2tff(buf[k4+3] * inv));
        *(float4*)(row + k4) = v;
    }
}

// ---------------------------------------------------------------------------
extern "C" void kernel_launch(void* const* d_in, const int* in_sizes, int n_in,
                              void* d_out, int out_size)
{
    (void)in_sizes; (void)n_in; (void)out_size;

    const float* x_batch = (const float*)d_in[0];
    const float* lin_w   = (const float*)d_in[1];
    const float* lin_b   = (const float*)d_in[2];
    const float* W_q     = (const float*)d_in[3];
    const float* W_k     = (const float*)d_in[4];
    const float* W_v     = (const float*)d_in[5];

    float* F  = (float*)d_out;
    float* cK = F  + (size_t)MTOT * D_;
    float* cV = cK + (size_t)MTOT * D_;

    float *xbh,*xbl,*xh,*xl,*kh,*kl,*vr,*sc;
    float *w0h,*w0l,*wqh,*wql,*wkh,*wkl,*wvh,*wvl;
    cudaGetSymbolAddress((void**)&xbh, g_xbh); cudaGetSymbolAddress((void**)&xbl, g_xbl);
    cudaGetSymbolAddress((void**)&xh,  g_xh);  cudaGetSymbolAddress((void**)&xl,  g_xl);
    cudaGetSymbolAddress((void**)&kh,  g_kh);  cudaGetSymbolAddress((void**)&kl,  g_kl);
    cudaGetSymbolAddress((void**)&vr,  g_vr);  cudaGetSymbolAddress((void**)&sc,  g_s);
    cudaGetSymbolAddress((void**)&w0h, g_w0h); cudaGetSymbolAddress((void**)&w0l, g_w0l);
    cudaGetSymbolAddress((void**)&wqh, g_wqh); cudaGetSymbolAddress((void**)&wql, g_wql);
    cudaGetSymbolAddress((void**)&wkh, g_wkh); cudaGetSymbolAddress((void**)&wkl, g_wkl);
    cudaGetSymbolAddress((void**)&wvh, g_wvh); cudaGetSymbolAddress((void**)&wvl, g_wvl);

    const int SMEM3 = 2 * 4 * 8192;   // 64KB
    const int SMEM1 = 2 * 2 * 8192;   // 32KB
    cudaFuncSetAttribute(mma_gemm<3, true,  false, false>,
                         cudaFuncAttributeMaxDynamicSharedMemorySize, SMEM3);
    cudaFuncSetAttribute(mma_gemm<3, false, false, false>,
                         cudaFuncAttributeMaxDynamicSharedMemorySize, SMEM3);
    cudaFuncSetAttribute(mma_gemm<3, true,  true,  false>,
                         cudaFuncAttributeMaxDynamicSharedMemorySize, SMEM3);
    cudaFuncSetAttribute(mma_gemm<1, false, false, true>,
                         cudaFuncAttributeMaxDynamicSharedMemorySize, SMEM1);

    const dim3 blk(256);

    // 0) splits
    split_k<<<MTOT * D_ / 4 / 256, blk>>>((const float4*)x_batch,
                                          (float4*)xbh, (float4*)xbl, MTOT * D_ / 4);
    split_k<<<D_ * D_ / 4 / 256, blk>>>((const float4*)lin_w, (float4*)w0h, (float4*)w0l, D_ * D_ / 4);
    split_k<<<D_ * D_ / 4 / 256, blk>>>((const float4*)W_q,   (float4*)wqh, (float4*)wql, D_ * D_ / 4);
    split_k<<<D_ * D_ / 4 / 256, blk>>>((const float4*)W_k,   (float4*)wkh, (float4*)wkl, D_ * D_ / 4);
    split_k<<<D_ * D_ / 4 / 256, blk>>>((const float4*)W_v,   (float4*)wvh, (float4*)wvl, D_ * D_ / 4);

    // 1) x planes = xb @ lin_w^T + b  (NT)
    mma_gemm<3, true, false, false><<<dim3(D_ / BN, MTOT / BM), blk, SMEM3>>>(
        xbh, xbl, w0h, w0l, lin_b, nullptr, xh, xl, nullptr, D_, D_, 0, 0, 0);
    // 2) Q planes (NN) -> reuse xb buffers
    mma_gemm<3, false, false, false><<<dim3(D_ / BN, MTOT / BM), blk, SMEM3>>>(
        xh, xl, wqh, wql, nullptr, nullptr, xbh, xbl, nullptr, D_, D_, 0, 0, 0);
    // 3) K: exact cache + planes (NN)
    mma_gemm<3, false, false, false><<<dim3(D_ / BN, MTOT / BM), blk, SMEM3>>>(
        xh, xl, wkh, wkl, nullptr, cK, kh, kl, nullptr, D_, D_, 0, 0, 0);
    // 4) V: exact cache + rounded plane (NN)
    mma_gemm<3, false, false, false><<<dim3(D_ / BN, MTOT / BM), blk, SMEM3>>>(
        xh, xl, wvh, wvl, nullptr, cV, nullptr, nullptr, vr, D_, D_, 0, 0, 0);
    // 5) S = Q @ K^T per batch (NT, causal block skip)
    mma_gemm<3, true, true, false><<<dim3(S_ / BN, S_ / BM, B_), blk, SMEM3>>>(
        xbh, xbl, kh, kl, nullptr, sc, nullptr, nullptr, nullptr, S_, D_,
        (size_t)S_ * D_, (size_t)S_ * D_, (size_t)S_ * S_);
    // 6) P = causal_softmax(S), rounded
    softmax_causal_kernel<<<dim3(S_, B_), blk>>>(sc);
    // 7) F = P @ V (NN, 1x tf32, causal K limit)
    mma_gemm<1, false, false, true><<<dim3(D_ / BN, S_ / BM, B_), blk, SMEM1>>>(
        sc, nullptr, vr, nullptr, nullptr, F, nullptr, nullptr, nullptr, D_, S_,
        (size_t)S_ * S_, (size_t)S_ * D_, (size_t)S_ * D_);
}